// round 9
// baseline (speedup 1.0000x reference)
#include <cuda_runtime.h>
#include <math.h>

typedef unsigned long long ull;

#define CB 32
#define CT 40
#define CP 12
#define CE 2048
#define CH 1024
#define CM (CB*CT*CP)     /* 15360 rows (b,t,p) */
#define CBP (CB*CP)       /* 384 GRU state rows */
#define CBT (CB*CT)       /* 1280 */

/* ---------------- scratch (device globals) ------------------------------- */
__device__ float g_x   [CM * CH];         /* embed out, row-major [M][H]   */
__device__ float g_gxT [3 * CH * CM];     /* gates^T  [3H][grow]           */
__device__ float g_hidT[CH * CM];         /* hiddens^T [H][grow]           */
__device__ float g_hT0 [CH * CBP];        /* h state^T [H][m]              */
__device__ float g_hT1 [CH * CBP];
__device__ float g_WhhT[CH * 3 * CH];     /* W_hh^T    [K][3H]             */
__device__ float g_pool[CH * CBT];        /* pooled^T  [H][bt]             */

/* ---------------- packed fp32x2 FMA -------------------------------------- */
__device__ __forceinline__ void ffma2(ull& d, ull a, ull b) {
    asm("fma.rn.f32x2 %0, %1, %2, %0;" : "+l"(d) : "l"(a), "l"(b));
}
__device__ __forceinline__ float2 upk(ull v) {
    return *reinterpret_cast<float2*>(&v);
}

/* ================= big GEMM (R7-proven, single-buffered) =================
 * C[m,n] = act(A[m,:]·W[n,:] + b[n]); A [M][K], W [N][K] row-major.
 * 128x128 tile, BK=8, 256 threads, acc paired along M, W duplicated.      */
#define BM 128
#define BN 128
#define BKc 8

__global__ __launch_bounds__(256) void gemm_f32x2(
    const float* __restrict__ A, const float* __restrict__ W,
    const float* __restrict__ bias, float* __restrict__ C,
    int N, int K, int act)
{
    __shared__ __align__(16) float As[BKc][BM + 4];
    __shared__ __align__(16) float Bs[BKc][2*BN + 8];

    const int tid = threadIdx.x;
    const int tx  = tid & 15;
    const int ty  = tid >> 4;
    const int lr  = tid >> 1;
    const int lk  = (tid & 1) << 2;

    const float* Ag = A + (size_t)(blockIdx.y * BM + lr) * K + lk;
    const float* Wg = W + (size_t)(blockIdx.x * BN + lr) * K + lk;

    ull acc[4][8];
#pragma unroll
    for (int i = 0; i < 4; i++)
#pragma unroll
        for (int j = 0; j < 8; j++) acc[i][j] = 0ULL;

    float4 pa = *(const float4*)Ag;
    float4 pb = *(const float4*)Wg;

    const int nch = K / BKc;
    for (int c = 0; c < nch; ++c) {
        __syncthreads();
        As[lk+0][lr] = pa.x;
        As[lk+1][lr] = pa.y;
        As[lk+2][lr] = pa.z;
        As[lk+3][lr] = pa.w;
        *(float2*)&Bs[lk+0][2*lr] = make_float2(pb.x, pb.x);
        *(float2*)&Bs[lk+1][2*lr] = make_float2(pb.y, pb.y);
        *(float2*)&Bs[lk+2][2*lr] = make_float2(pb.z, pb.z);
        *(float2*)&Bs[lk+3][2*lr] = make_float2(pb.w, pb.w);
        __syncthreads();
        if (c + 1 < nch) {
            pa = *(const float4*)(Ag + (size_t)(c+1)*BKc);
            pb = *(const float4*)(Wg + (size_t)(c+1)*BKc);
        }
#pragma unroll
        for (int kk = 0; kk < BKc; ++kk) {
            ulonglong2 a0 = *(const ulonglong2*)&As[kk][ty*8];
            ulonglong2 a1 = *(const ulonglong2*)&As[kk][ty*8 + 4];
            ull am[4] = {a0.x, a0.y, a1.x, a1.y};
            ull bd[8];
#pragma unroll
            for (int q = 0; q < 4; q++) {
                ulonglong2 bq = *(const ulonglong2*)&Bs[kk][q*64 + 4*tx];
                bd[2*q]   = bq.x;
                bd[2*q+1] = bq.y;
            }
#pragma unroll
            for (int mp = 0; mp < 4; mp++)
#pragma unroll
                for (int n = 0; n < 8; n++) ffma2(acc[mp][n], am[mp], bd[n]);
        }
    }

    const int colb = blockIdx.x * BN;
    float2 bb[4];
#pragma unroll
    for (int q = 0; q < 4; q++)
        bb[q] = *(const float2*)&bias[colb + 32*q + 2*tx];
#pragma unroll
    for (int mp = 0; mp < 4; mp++) {
#pragma unroll
        for (int half = 0; half < 2; half++) {
            int row = blockIdx.y * BM + ty*8 + 2*mp + half;
            float* Cr = C + (size_t)row * N + colb;
#pragma unroll
            for (int q = 0; q < 4; q++) {
                float2 e = upk(acc[mp][2*q]);
                float2 o = upk(acc[mp][2*q+1]);
                float2 v;
                v.x = (half ? e.y : e.x) + bb[q].x;
                v.y = (half ? o.y : o.x) + bb[q].y;
                if (act) { v.x = tanhf(v.x); v.y = tanhf(v.y); }
                *(float2*)&Cr[32*q + 2*tx] = v;
            }
        }
    }
}

/* ============ same GEMM but epilogue writes C TRANSPOSED [N][M] ========== */
__global__ __launch_bounds__(256) void gemm_f32x2_ct(
    const float* __restrict__ A, const float* __restrict__ W,
    const float* __restrict__ bias, float* __restrict__ Ct,
    int N, int M, int K)
{
    __shared__ __align__(16) float As[BKc][BM + 4];
    __shared__ __align__(16) float Bs[BKc][2*BN + 8];

    const int tid = threadIdx.x;
    const int tx  = tid & 15;
    const int ty  = tid >> 4;
    const int lr  = tid >> 1;
    const int lk  = (tid & 1) << 2;

    const float* Ag = A + (size_t)(blockIdx.y * BM + lr) * K + lk;
    const float* Wg = W + (size_t)(blockIdx.x * BN + lr) * K + lk;

    ull acc[4][8];
#pragma unroll
    for (int i = 0; i < 4; i++)
#pragma unroll
        for (int j = 0; j < 8; j++) acc[i][j] = 0ULL;

    float4 pa = *(const float4*)Ag;
    float4 pb = *(const float4*)Wg;

    const int nch = K / BKc;
    for (int c = 0; c < nch; ++c) {
        __syncthreads();
        As[lk+0][lr] = pa.x;
        As[lk+1][lr] = pa.y;
        As[lk+2][lr] = pa.z;
        As[lk+3][lr] = pa.w;
        *(float2*)&Bs[lk+0][2*lr] = make_float2(pb.x, pb.x);
        *(float2*)&Bs[lk+1][2*lr] = make_float2(pb.y, pb.y);
        *(float2*)&Bs[lk+2][2*lr] = make_float2(pb.z, pb.z);
        *(float2*)&Bs[lk+3][2*lr] = make_float2(pb.w, pb.w);
        __syncthreads();
        if (c + 1 < nch) {
            pa = *(const float4*)(Ag + (size_t)(c+1)*BKc);
            pb = *(const float4*)(Wg + (size_t)(c+1)*BKc);
        }
#pragma unroll
        for (int kk = 0; kk < BKc; ++kk) {
            ulonglong2 a0 = *(const ulonglong2*)&As[kk][ty*8];
            ulonglong2 a1 = *(const ulonglong2*)&As[kk][ty*8 + 4];
            ull am[4] = {a0.x, a0.y, a1.x, a1.y};
            ull bd[8];
#pragma unroll
            for (int q = 0; q < 4; q++) {
                ulonglong2 bq = *(const ulonglong2*)&Bs[kk][q*64 + 4*tx];
                bd[2*q]   = bq.x;
                bd[2*q+1] = bq.y;
            }
#pragma unroll
            for (int mp = 0; mp < 4; mp++)
#pragma unroll
                for (int n = 0; n < 8; n++) ffma2(acc[mp][n], am[mp], bd[n]);
        }
    }

    /* transposed epilogue: thread owns 8 consecutive rows per column */
    const int colb = blockIdx.x * BN;
    const int row0 = blockIdx.y * BM + ty*8;
#pragma unroll
    for (int q = 0; q < 4; q++) {
#pragma unroll
        for (int jj = 0; jj < 2; jj++) {
            int col = colb + 32*q + 2*tx + jj;
            float bi = bias[col];
            float v[8];
#pragma unroll
            for (int mp = 0; mp < 4; mp++) {
                float2 e = upk(acc[mp][2*q + jj]);
                v[2*mp]   = e.x + bi;
                v[2*mp+1] = e.y + bi;
            }
            *(float4*)&Ct[(size_t)col * M + row0]     = make_float4(v[0], v[1], v[2], v[3]);
            *(float4*)&Ct[(size_t)col * M + row0 + 4] = make_float4(v[4], v[5], v[6], v[7]);
        }
    }
}

/* ================= 32x32 transpose: W[R][C] -> WT[C][R] ================== */
__global__ __launch_bounds__(256) void transpose_k(
    const float* __restrict__ src, float* __restrict__ dst, int R, int C)
{
    __shared__ float tbuf[32][33];
    int c0 = blockIdx.x * 32, r0 = blockIdx.y * 32;
    int lx = threadIdx.x & 31, lyb = (threadIdx.x >> 5) * 4;
#pragma unroll
    for (int i = 0; i < 4; i++)
        tbuf[lyb + i][lx] = src[(size_t)(r0 + lyb + i) * C + c0 + lx];
    __syncthreads();
#pragma unroll
    for (int i = 0; i < 4; i++)
        dst[(size_t)(c0 + lyb + i) * R + r0 + lx] = tbuf[lx][lyb + i];
}

/* ================= fused GRU step (k-major, coalesced) ===================
 * Tile 96m x 32j x 3 gates, 192 threads, grid (32 j, 4 m) = 128 blocks.
 * Loads per chunk: each thread ONE float4 of hT and ONE of WhhT, fully
 * coalesced (warp reads contiguous k-rows). A natural smem, W dup (w,w).
 * Per kk: 2 a-LDS.128 + 3 b-LDS.128 + 24 FFMA2.                          */
#define GRM 96

__global__ __launch_bounds__(192) void gru_step(
    const float* __restrict__ hT_in, float* __restrict__ hT_out,
    const float* __restrict__ gxT, const float* __restrict__ WhhT,
    const float* __restrict__ b_hh, float* __restrict__ hidT, int t)
{
    __shared__ __align__(16) float As[BKc][100];      /* [k][m], stride 100 */
    __shared__ __align__(16) float Bs[BKc][200];      /* dup cols, stride 200 */

    const int tid = threadIdx.x;
    const int tx  = tid & 15;          /* col pair: 2tx, 2tx+1   */
    const int ty  = tid >> 4;          /* 0..11: rows 8ty..8ty+7 */
    const int m0  = blockIdx.y * GRM;
    const int j0  = blockIdx.x * 32;

    /* loaders: thread -> (k-row = tid/24, 24 threads cover one 96-float row) */
    const int akr = tid / 24;
    const int s   = tid - akr * 24;
    const int ac4 = s * 4;
    const int gg  = s >> 3;            /* gate strip 0..2 */
    const int uu  = s & 7;             /* 4-col group     */

    const float* Ag = hT_in + (size_t)akr * CBP + m0 + ac4;
    const float* Wg = WhhT + (size_t)akr * (3*CH) + gg*CH + j0 + uu*4;

    ull acc[4][3][2];
#pragma unroll
    for (int i = 0; i < 4; i++)
#pragma unroll
        for (int g = 0; g < 3; g++) { acc[i][g][0] = 0ULL; acc[i][g][1] = 0ULL; }

    if (t > 0) {   /* t==0: h=0 -> gh = 0 (+bias in epilogue); skip GEMM */
        float4 pa = *(const float4*)Ag;
        float4 pb = *(const float4*)Wg;
        const int nch = CH / BKc;   /* 128 */
        for (int c = 0; c < nch; ++c) {
            __syncthreads();
            *(float4*)&As[akr][ac4] = pa;
            *(float4*)&Bs[akr][gg*64 + uu*8]     = make_float4(pb.x, pb.x, pb.y, pb.y);
            *(float4*)&Bs[akr][gg*64 + uu*8 + 4] = make_float4(pb.z, pb.z, pb.w, pb.w);
            __syncthreads();
            if (c + 1 < nch) {
                pa = *(const float4*)(Ag + (size_t)(c+1)*BKc*CBP);
                pb = *(const float4*)(Wg + (size_t)(c+1)*BKc*(3*CH));
            }
#pragma unroll
            for (int kk = 0; kk < BKc; ++kk) {
                ulonglong2 a0 = *(const ulonglong2*)&As[kk][ty*8];
                ulonglong2 a1 = *(const ulonglong2*)&As[kk][ty*8 + 4];
                ull am[4] = {a0.x, a0.y, a1.x, a1.y};
                ull bd[3][2];
#pragma unroll
                for (int g = 0; g < 3; g++) {
                    ulonglong2 bq = *(const ulonglong2*)&Bs[kk][g*64 + 4*tx];
                    bd[g][0] = bq.x;
                    bd[g][1] = bq.y;
                }
#pragma unroll
                for (int mp = 0; mp < 4; mp++)
#pragma unroll
                    for (int g = 0; g < 3; g++) {
                        ffma2(acc[mp][g][0], am[mp], bd[g][0]);
                        ffma2(acc[mp][g][1], am[mp], bd[g][1]);
                    }
            }
        }
    }

    /* epilogue: per thread 2 columns x 8 consecutive m-rows */
    const int mb = m0 + ty*8;
#pragma unroll
    for (int jj = 0; jj < 2; jj++) {
        const int colj = j0 + 2*tx + jj;
        const float bhr = b_hh[colj];
        const float bhz = b_hh[CH  + colj];
        const float bhn = b_hh[2*CH + colj];
        float gr[8], gz[8], gn[8];
#pragma unroll
        for (int mp = 0; mp < 4; mp++) {
            float2 vr = upk(acc[mp][0][jj]);
            float2 vz = upk(acc[mp][1][jj]);
            float2 vn = upk(acc[mp][2][jj]);
            gr[2*mp] = vr.x; gr[2*mp+1] = vr.y;
            gz[2*mp] = vz.x; gz[2*mp+1] = vz.y;
            gn[2*mp] = vn.x; gn[2*mp+1] = vn.y;
        }
        float4 h0 = *(const float4*)&hT_in[(size_t)colj * CBP + mb];
        float4 h1 = *(const float4*)&hT_in[(size_t)colj * CBP + mb + 4];
        float ho[8] = {h0.x, h0.y, h0.z, h0.w, h1.x, h1.y, h1.z, h1.w};
        float hn[8];
#pragma unroll
        for (int i = 0; i < 8; i++) {
            int m = mb + i;
            int b = m / CP, p = m - b * CP;
            size_t grow = (size_t)(b * CT + t) * CP + p;
            float xr = gxT[(size_t)colj * CM + grow];
            float xz = gxT[(size_t)(CH + colj) * CM + grow];
            float xn = gxT[(size_t)(2*CH + colj) * CM + grow];
            float r = 1.f / (1.f + expf(-(xr + gr[i] + bhr)));
            float z = 1.f / (1.f + expf(-(xz + gz[i] + bhz)));
            float n = tanhf(xn + r * (gn[i] + bhn));
            hn[i] = (1.f - z) * n + z * ho[i];
            hidT[(size_t)colj * CM + grow] = hn[i];
        }
        *(float4*)&hT_out[(size_t)colj * CBP + mb]     = make_float4(hn[0], hn[1], hn[2], hn[3]);
        *(float4*)&hT_out[(size_t)colj * CBP + mb + 4] = make_float4(hn[4], hn[5], hn[6], hn[7]);
    }
}

/* ---------------- heads (hidT consumers) --------------------------------- */
/* action logits: out[grow][a] = sum_j hidT[j][grow]*W[a][j] + b[a] */
__global__ __launch_bounds__(128) void action_head(
    const float* __restrict__ hidT, const float* __restrict__ W,
    const float* __restrict__ bias, float* __restrict__ out)
{
    __shared__ float Ws[9 * CH];
    for (int i = threadIdx.x; i < 9 * CH; i += 128) Ws[i] = W[i];
    __syncthreads();
    const int warp = threadIdx.x >> 5, lane = threadIdx.x & 31;
    const size_t g0 = (size_t)(blockIdx.x * 4 + warp) * 32 + lane;
    float p[9];
#pragma unroll
    for (int a = 0; a < 9; a++) p[a] = 0.f;
#pragma unroll 4
    for (int j = 0; j < CH; j++) {
        float v = hidT[(size_t)j * CM + g0];
#pragma unroll
        for (int a = 0; a < 9; a++) p[a] += v * Ws[a*CH + j];
    }
#pragma unroll
    for (int a = 0; a < 9; a++) out[g0 * 9 + a] = p[a] + bias[a];
}

/* max-pool over persons: pooled[j][bt] = max_p hidT[j][(bt)*12+p] */
__global__ __launch_bounds__(256) void pool_kernel(
    const float* __restrict__ hidT, float* __restrict__ pooled)
{
    int id = blockIdx.x * 256 + threadIdx.x;
    if (id >= CH * CBT) return;
    int j = id / CBT, bt = id - j * CBT;
    const float* base = hidT + (size_t)j * CM + (size_t)bt * CP;
    float4 a = *(const float4*)(base);
    float4 b = *(const float4*)(base + 4);
    float4 c = *(const float4*)(base + 8);
    float v = fmaxf(fmaxf(fmaxf(a.x, a.y), fmaxf(a.z, a.w)),
             fmaxf(fmaxf(fmaxf(b.x, b.y), fmaxf(b.z, b.w)),
                   fmaxf(fmaxf(c.x, c.y), fmaxf(c.z, c.w))));
    pooled[(size_t)j * CBT + bt] = v;
}

/* activity logits: out2[bt][a] = sum_j pooled[j][bt]*W[a][j] + b[a] */
__global__ __launch_bounds__(128) void activity_head(
    const float* __restrict__ pooled, const float* __restrict__ W,
    const float* __restrict__ bias, float* __restrict__ out2)
{
    __shared__ float Ws[8 * CH];
    for (int i = threadIdx.x; i < 8 * CH; i += 128) Ws[i] = W[i];
    __syncthreads();
    const int warp = threadIdx.x >> 5, lane = threadIdx.x & 31;
    const int bt = (blockIdx.x * 4 + warp) * 32 + lane;
    float p[8];
#pragma unroll
    for (int a = 0; a < 8; a++) p[a] = 0.f;
#pragma unroll 4
    for (int j = 0; j < CH; j++) {
        float v = pooled[(size_t)j * CBT + bt];
#pragma unroll
        for (int a = 0; a < 8; a++) p[a] += v * Ws[a*CH + j];
    }
#pragma unroll
    for (int a = 0; a < 8; a++) out2[(size_t)bt * 8 + a] = p[a] + bias[a];
}

__global__ void zero_kernel(float* p, int n) {
    int i = blockIdx.x * 256 + threadIdx.x;
    if (i < n) p[i] = 0.f;
}

/* ---------------- launcher ----------------------------------------------- */
extern "C" void kernel_launch(void* const* d_in, const int* in_sizes, int n_in,
                              void* d_out, int out_size)
{
    const float* feature = (const float*)d_in[0];
    const float* W_embed = (const float*)d_in[1];
    const float* b_embed = (const float*)d_in[2];
    const float* W_ih    = (const float*)d_in[3];
    const float* W_hh    = (const float*)d_in[4];
    const float* b_ih    = (const float*)d_in[5];
    const float* b_hh    = (const float*)d_in[6];
    const float* W_act   = (const float*)d_in[7];
    const float* b_act   = (const float*)d_in[8];
    const float* W_activ = (const float*)d_in[9];
    const float* b_activ = (const float*)d_in[10];
    float* out = (float*)d_out;

    float *px, *pgxT, *phidT, *phT0, *phT1, *pWhhT, *ppool;
    cudaGetSymbolAddress((void**)&px,    g_x);
    cudaGetSymbolAddress((void**)&pgxT,  g_gxT);
    cudaGetSymbolAddress((void**)&phidT, g_hidT);
    cudaGetSymbolAddress((void**)&phT0,  g_hT0);
    cudaGetSymbolAddress((void**)&phT1,  g_hT1);
    cudaGetSymbolAddress((void**)&pWhhT, g_WhhT);
    cudaGetSymbolAddress((void**)&ppool, g_pool);

    /* h0 = 0 (t=0 reads hold from it) */
    zero_kernel<<<(CH*CBP + 255)/256, 256>>>(phT0, CH*CBP);

    /* W_hh^T: [3072][1024] -> [1024][3072] */
    transpose_k<<<dim3(CH/32, 3*CH/32), 256>>>(W_hh, pWhhT, 3*CH, CH);

    /* x = tanh(feature @ W_embed^T + b)   [15360][1024] row-major */
    gemm_f32x2<<<dim3(CH/BN, CM/BM), 256>>>(feature, W_embed, b_embed, px,
                                            CH, CE, 1);
    /* gxT = (x @ W_ih^T + b)^T            [3072][15360] */
    gemm_f32x2_ct<<<dim3(3*CH/BN, CM/BM), 256>>>(px, W_ih, b_ih, pgxT,
                                                 3*CH, CM, CH);

    /* GRU scan, double-buffered transposed state */
    float* hin = phT0;
    float* hout = phT1;
    for (int t = 0; t < CT; ++t) {
        gru_step<<<dim3(CH/32, CBP/GRM), 192>>>(hin, hout, pgxT, pWhhT, b_hh,
                                                phidT, t);
        float* tmp = hin; hin = hout; hout = tmp;
    }

    /* heads */
    action_head<<<CM/128, 128>>>(phidT, W_act, b_act, out);
    pool_kernel<<<(CH*CBT + 255)/256, 256>>>(phidT, ppool);
    activity_head<<<CBT/128, 128>>>(ppool, W_activ, b_activ,
                                    out + (size_t)CM * 9);
}

// round 10
// speedup vs baseline: 1.4866x; 1.4866x over previous
#include <cuda_runtime.h>
#include <math.h>

typedef unsigned long long ull;

#define CB 32
#define CT 40
#define CP 12
#define CE 2048
#define CH 1024
#define CM (CB*CT*CP)     /* 15360 rows of (b,t,p) */
#define CBP (CB*CP)       /* 384 GRU state rows */

/* ---------------- scratch (device globals; no allocation allowed) -------- */
__device__ float g_x  [CM * CH];        /* embed output          */
__device__ float g_gx [CM * 3 * CH];    /* input gates           */
__device__ float g_hid[CM * CH];        /* all hiddens           */
__device__ float g_h0 [CBP * CH];
__device__ float g_h1 [CBP * CH];

/* ---------------- packed fp32x2 FMA (Blackwell FFMA2) -------------------- */
__device__ __forceinline__ void ffma2(ull& d, ull a, ull b) {
    asm("fma.rn.f32x2 %0, %1, %2, %0;" : "+l"(d) : "l"(a), "l"(b));
}
__device__ __forceinline__ float2 upk(ull v) {
    return *reinterpret_cast<float2*>(&v);
}

/* ================= big GEMM: C[m,n] = act(A[m,:]·W[n,:] + b[n]) ==========
 * Tile 128x128, BK=16, 256 threads. acc paired along M; A natural smem
 * (broadcast LDS.128), W duplicated (w,w) -> conflict-free LDS.128 covers
 * two adjacent cols. Loaders: 4 threads/row read 64B contiguous ->
 * 8 lines/warp-LDG (2x better than BK=8).                                 */
#define BM 128
#define BN 128
#define BKg 16

__global__ __launch_bounds__(256) void gemm_f32x2(
    const float* __restrict__ A, const float* __restrict__ W,
    const float* __restrict__ bias, float* __restrict__ C,
    int N, int K, int act)
{
    __shared__ __align__(16) float As[BKg][BM + 4];
    __shared__ __align__(16) float Bs[BKg][2*BN + 8];

    const int tid = threadIdx.x;
    const int tx  = tid & 15;          /* col group            */
    const int ty  = tid >> 4;          /* rows ty*8..ty*8+7    */
    const int lr  = tid >> 2;          /* loader row 0..63     */
    const int lk  = (tid & 3) << 2;    /* loader k: 0,4,8,12   */

    const float* Ag0 = A + (size_t)(blockIdx.y * BM + lr) * K + lk;
    const float* Ag1 = Ag0 + (size_t)64 * K;
    const float* Wg0 = W + (size_t)(blockIdx.x * BN + lr) * K + lk;
    const float* Wg1 = Wg0 + (size_t)64 * K;

    ull acc[4][8];
#pragma unroll
    for (int i = 0; i < 4; i++)
#pragma unroll
        for (int j = 0; j < 8; j++) acc[i][j] = 0ULL;

    float4 pa0 = *(const float4*)Ag0;
    float4 pa1 = *(const float4*)Ag1;
    float4 pb0 = *(const float4*)Wg0;
    float4 pb1 = *(const float4*)Wg1;

    const int nch = K / BKg;           /* 128 or 64 */
    for (int c = 0; c < nch; ++c) {
        __syncthreads();
        As[lk+0][lr] = pa0.x;  As[lk+1][lr] = pa0.y;
        As[lk+2][lr] = pa0.z;  As[lk+3][lr] = pa0.w;
        As[lk+0][lr+64] = pa1.x;  As[lk+1][lr+64] = pa1.y;
        As[lk+2][lr+64] = pa1.z;  As[lk+3][lr+64] = pa1.w;
        *(float2*)&Bs[lk+0][2*lr] = make_float2(pb0.x, pb0.x);
        *(float2*)&Bs[lk+1][2*lr] = make_float2(pb0.y, pb0.y);
        *(float2*)&Bs[lk+2][2*lr] = make_float2(pb0.z, pb0.z);
        *(float2*)&Bs[lk+3][2*lr] = make_float2(pb0.w, pb0.w);
        *(float2*)&Bs[lk+0][2*(lr+64)] = make_float2(pb1.x, pb1.x);
        *(float2*)&Bs[lk+1][2*(lr+64)] = make_float2(pb1.y, pb1.y);
        *(float2*)&Bs[lk+2][2*(lr+64)] = make_float2(pb1.z, pb1.z);
        *(float2*)&Bs[lk+3][2*(lr+64)] = make_float2(pb1.w, pb1.w);
        __syncthreads();
        if (c + 1 < nch) {
            size_t off = (size_t)(c+1) * BKg;
            pa0 = *(const float4*)(Ag0 + off);
            pa1 = *(const float4*)(Ag1 + off);
            pb0 = *(const float4*)(Wg0 + off);
            pb1 = *(const float4*)(Wg1 + off);
        }
#pragma unroll 8
        for (int kk = 0; kk < BKg; ++kk) {
            ulonglong2 a0 = *(const ulonglong2*)&As[kk][ty*8];
            ulonglong2 a1 = *(const ulonglong2*)&As[kk][ty*8 + 4];
            ull am[4] = {a0.x, a0.y, a1.x, a1.y};
            ull bd[8];
#pragma unroll
            for (int q = 0; q < 4; q++) {
                ulonglong2 bq = *(const ulonglong2*)&Bs[kk][q*64 + 4*tx];
                bd[2*q]   = bq.x;
                bd[2*q+1] = bq.y;
            }
#pragma unroll
            for (int mp = 0; mp < 4; mp++)
#pragma unroll
                for (int n = 0; n < 8; n++) ffma2(acc[mp][n], am[mp], bd[n]);
        }
    }

    /* epilogue: acc[mp][2q+jj] = (row 2mp, row 2mp+1) at col 32q+2tx+jj */
    const int colb = blockIdx.x * BN;
    float2 bb[4];
#pragma unroll
    for (int q = 0; q < 4; q++)
        bb[q] = *(const float2*)&bias[colb + 32*q + 2*tx];
#pragma unroll
    for (int mp = 0; mp < 4; mp++) {
#pragma unroll
        for (int half = 0; half < 2; half++) {
            int row = blockIdx.y * BM + ty*8 + 2*mp + half;
            float* Cr = C + (size_t)row * N + colb;
#pragma unroll
            for (int q = 0; q < 4; q++) {
                float2 e = upk(acc[mp][2*q]);
                float2 o = upk(acc[mp][2*q+1]);
                float2 v;
                v.x = (half ? e.y : e.x) + bb[q].x;
                v.y = (half ? o.y : o.x) + bb[q].y;
                if (act) { v.x = tanhf(v.x); v.y = tanhf(v.y); }
                *(float2*)&Cr[32*q + 2*tx] = v;
            }
        }
    }
}

/* ================= fused GRU step ========================================
 * Tile 96m x 32j x 3 gates, 192 threads, grid (32, 4) = 128 blocks.
 * BK=32: loaders put 8 threads on one row reading 128B contiguous ->
 * 4 lines/warp-LDG (4x better than R7's 16). Same dense core:
 * 2 a-LDS + 3 b-LDS + 24 FFMA2 per kk. R7's coalesced epilogue/layouts.  */
#define GRM 96
#define GBK 32

__global__ __launch_bounds__(192) void gru_step(
    const float* __restrict__ h_in, float* __restrict__ h_out,
    const float* __restrict__ gx, const float* __restrict__ W_hh,
    const float* __restrict__ b_hh, float* __restrict__ hid, int t)
{
    __shared__ __align__(16) float As[GBK][GRM + 4];     /* h, natural   */
    __shared__ __align__(16) float Bs[GBK][192 + 8];     /* W, dup (w,w) */

    const int tid = threadIdx.x;
    const int tx  = tid & 15;          /* col pair: 2tx, 2tx+1 per gate */
    const int ty  = tid >> 4;          /* 0..11: rows 8ty..8ty+7        */
    const int m0  = blockIdx.y * GRM;
    const int j0  = blockIdx.x * 32;

    const int lr8 = tid >> 3;          /* 0..23 */
    const int lk  = (tid & 7) << 2;    /* 0..28 */

    const float* Ag[4];
    const float* Wg[4];
    int brow[4];
#pragma unroll
    for (int p = 0; p < 4; p++) {
        int ar = p*24 + lr8;                              /* 0..95 */
        Ag[p] = h_in + (size_t)(m0 + ar) * CH + lk;
        brow[p] = ar;
        int g = ar >> 5, jj = ar & 31;
        Wg[p] = W_hh + (size_t)(g * CH + j0 + jj) * CH + lk;
    }

    ull acc[4][3][2];
#pragma unroll
    for (int i = 0; i < 4; i++)
#pragma unroll
        for (int g = 0; g < 3; g++) { acc[i][g][0] = 0ULL; acc[i][g][1] = 0ULL; }

    float4 pa[4], pb[4];
#pragma unroll
    for (int p = 0; p < 4; p++) {
        pa[p] = *(const float4*)Ag[p];
        pb[p] = *(const float4*)Wg[p];
    }

    const int nch = CH / GBK;   /* 32 */
    for (int c = 0; c < nch; ++c) {
        __syncthreads();
#pragma unroll
        for (int p = 0; p < 4; p++) {
            int ar = p*24 + lr8;
            As[lk+0][ar] = pa[p].x;  As[lk+1][ar] = pa[p].y;
            As[lk+2][ar] = pa[p].z;  As[lk+3][ar] = pa[p].w;
            *(float2*)&Bs[lk+0][2*brow[p]] = make_float2(pb[p].x, pb[p].x);
            *(float2*)&Bs[lk+1][2*brow[p]] = make_float2(pb[p].y, pb[p].y);
            *(float2*)&Bs[lk+2][2*brow[p]] = make_float2(pb[p].z, pb[p].z);
            *(float2*)&Bs[lk+3][2*brow[p]] = make_float2(pb[p].w, pb[p].w);
        }
        __syncthreads();
        if (c + 1 < nch) {
            size_t off = (size_t)(c+1) * GBK;
#pragma unroll
            for (int p = 0; p < 4; p++) {
                pa[p] = *(const float4*)(Ag[p] + off);
                pb[p] = *(const float4*)(Wg[p] + off);
            }
        }
#pragma unroll 8
        for (int kk = 0; kk < GBK; ++kk) {
            ulonglong2 a0 = *(const ulonglong2*)&As[kk][ty*8];
            ulonglong2 a1 = *(const ulonglong2*)&As[kk][ty*8 + 4];
            ull am[4] = {a0.x, a0.y, a1.x, a1.y};
            ull bd[3][2];
#pragma unroll
            for (int g = 0; g < 3; g++) {
                ulonglong2 bq = *(const ulonglong2*)&Bs[kk][g*64 + 4*tx];
                bd[g][0] = bq.x;
                bd[g][1] = bq.y;
            }
#pragma unroll
            for (int mp = 0; mp < 4; mp++)
#pragma unroll
                for (int g = 0; g < 3; g++) {
                    ffma2(acc[mp][g][0], am[mp], bd[g][0]);
                    ffma2(acc[mp][g][1], am[mp], bd[g][1]);
                }
        }
    }

    /* epilogue: GRU elementwise update (8 m-rows x 2 j-cols per thread) */
    const int jb = j0 + 2*tx;
    float2 bhr = *(const float2*)&b_hh[jb];
    float2 bhz = *(const float2*)&b_hh[CH + jb];
    float2 bhn = *(const float2*)&b_hh[2*CH + jb];
#pragma unroll
    for (int mp = 0; mp < 4; mp++) {
        float2 r0 = upk(acc[mp][0][0]), r1 = upk(acc[mp][0][1]);
        float2 z0 = upk(acc[mp][1][0]), z1 = upk(acc[mp][1][1]);
        float2 n0 = upk(acc[mp][2][0]), n1 = upk(acc[mp][2][1]);
#pragma unroll
        for (int half = 0; half < 2; half++) {
            int m = m0 + ty*8 + 2*mp + half;
            int b = m / CP, p = m - b * CP;
            size_t grow = (size_t)(b * CT + t) * CP + p;
            const float* gxr = gx + grow * (3*CH);
            float2 xr = *(const float2*)&gxr[jb];
            float2 xz = *(const float2*)&gxr[CH + jb];
            float2 xn = *(const float2*)&gxr[2*CH + jb];
            float2 hold = *(const float2*)&h_in[(size_t)m * CH + jb];
            float ghr0 = (half ? r0.y : r0.x) + bhr.x;
            float ghr1 = (half ? r1.y : r1.x) + bhr.y;
            float ghz0 = (half ? z0.y : z0.x) + bhz.x;
            float ghz1 = (half ? z1.y : z1.x) + bhz.y;
            float ghn0 = (half ? n0.y : n0.x) + bhn.x;
            float ghn1 = (half ? n1.y : n1.x) + bhn.y;
            float r_0 = 1.f / (1.f + expf(-(xr.x + ghr0)));
            float r_1 = 1.f / (1.f + expf(-(xr.y + ghr1)));
            float z_0 = 1.f / (1.f + expf(-(xz.x + ghz0)));
            float z_1 = 1.f / (1.f + expf(-(xz.y + ghz1)));
            float n_0 = tanhf(xn.x + r_0 * ghn0);
            float n_1 = tanhf(xn.y + r_1 * ghn1);
            float2 hn;
            hn.x = (1.f - z_0) * n_0 + z_0 * hold.x;
            hn.y = (1.f - z_1) * n_1 + z_1 * hold.y;
            *(float2*)&h_out[(size_t)m * CH + jb] = hn;
            *(float2*)&hid[grow * CH + jb]        = hn;
        }
    }
}

/* ---------------- heads (R7-proven) -------------------------------------- */
__global__ __launch_bounds__(256) void action_head(
    const float* __restrict__ hid, const float* __restrict__ W,
    const float* __restrict__ bias, float* __restrict__ out)
{
    __shared__ float Ws[9 * CH];
    for (int i = threadIdx.x; i < 9 * CH; i += 256) Ws[i] = W[i];
    __syncthreads();
    const int warp = threadIdx.x >> 5, lane = threadIdx.x & 31;
    const int m = blockIdx.x * 8 + warp;
    const float* hr = hid + (size_t)m * CH;
    float p[9];
#pragma unroll
    for (int a = 0; a < 9; a++) p[a] = 0.f;
    for (int kk = 0; kk < CH/32; kk++) {
        int k = lane + 32*kk;
        float v = hr[k];
#pragma unroll
        for (int a = 0; a < 9; a++) p[a] += v * Ws[a*CH + k];
    }
#pragma unroll
    for (int a = 0; a < 9; a++) {
        float s = p[a];
#pragma unroll
        for (int o = 16; o > 0; o >>= 1) s += __shfl_down_sync(0xffffffffu, s, o);
        if (lane == 0) out[(size_t)m * 9 + a] = s + bias[a];
    }
}

__global__ __launch_bounds__(256) void activity_head(
    const float* __restrict__ hid, const float* __restrict__ W,
    const float* __restrict__ bias, float* __restrict__ out)
{
    __shared__ float Ws[8 * CH];
    for (int i = threadIdx.x; i < 8 * CH; i += 256) Ws[i] = W[i];
    __syncthreads();
    const int warp = threadIdx.x >> 5, lane = threadIdx.x & 31;
    const int bt = blockIdx.x * 8 + warp;                 /* (b*T+t) */
    const float* base = hid + (size_t)bt * CP * CH;
    float p[8];
#pragma unroll
    for (int a = 0; a < 8; a++) p[a] = 0.f;
    for (int kk = 0; kk < CH/32; kk++) {
        int k = lane + 32*kk;
        float v = base[k];
#pragma unroll
        for (int pp = 1; pp < CP; pp++) v = fmaxf(v, base[(size_t)pp*CH + k]);
#pragma unroll
        for (int a = 0; a < 8; a++) p[a] += v * Ws[a*CH + k];
    }
#pragma unroll
    for (int a = 0; a < 8; a++) {
        float s = p[a];
#pragma unroll
        for (int o = 16; o > 0; o >>= 1) s += __shfl_down_sync(0xffffffffu, s, o);
        if (lane == 0) out[(size_t)bt * 8 + a] = s + bias[a];
    }
}

__global__ void zero_kernel(float* p, int n) {
    int i = blockIdx.x * 256 + threadIdx.x;
    if (i < n) p[i] = 0.f;
}

/* ---------------- launcher ----------------------------------------------- */
extern "C" void kernel_launch(void* const* d_in, const int* in_sizes, int n_in,
                              void* d_out, int out_size)
{
    const float* feature = (const float*)d_in[0];
    const float* W_embed = (const float*)d_in[1];
    const float* b_embed = (const float*)d_in[2];
    const float* W_ih    = (const float*)d_in[3];
    const float* W_hh    = (const float*)d_in[4];
    const float* b_ih    = (const float*)d_in[5];
    const float* b_hh    = (const float*)d_in[6];
    const float* W_act   = (const float*)d_in[7];
    const float* b_act   = (const float*)d_in[8];
    const float* W_activ = (const float*)d_in[9];
    const float* b_activ = (const float*)d_in[10];
    float* out = (float*)d_out;

    float *px, *pgx, *phid, *ph0, *ph1;
    cudaGetSymbolAddress((void**)&px,   g_x);
    cudaGetSymbolAddress((void**)&pgx,  g_gx);
    cudaGetSymbolAddress((void**)&phid, g_hid);
    cudaGetSymbolAddress((void**)&ph0,  g_h0);
    cudaGetSymbolAddress((void**)&ph1,  g_h1);

    /* h0 = 0 */
    zero_kernel<<<(CBP*CH + 255)/256, 256>>>(ph0, CBP*CH);

    /* x = tanh(feature @ W_embed^T + b_embed)  [15360,1024] */
    gemm_f32x2<<<dim3(CH/BN, CM/BM), 256>>>(feature, W_embed, b_embed, px,
                                            CH, CE, 1);
    /* gx = x @ W_ih^T + b_ih                   [15360,3072] */
    gemm_f32x2<<<dim3(3*CH/BN, CM/BM), 256>>>(px, W_ih, b_ih, pgx,
                                              3*CH, CH, 0);

    /* GRU scan, double-buffered state */
    float* hin = ph0;
    float* hout = ph1;
    for (int t = 0; t < CT; ++t) {
        gru_step<<<dim3(CH/32, CBP/GRM), 192>>>(hin, hout, pgx, W_hh, b_hh,
                                                phid, t);
        float* tmp = hin; hin = hout; hout = tmp;
    }

    /* heads: action logits [15360,9] then activity logits [1280,8] */
    action_head<<<CM/8, 256>>>(phid, W_act, b_act, out);
    activity_head<<<(CB*CT)/8, 256>>>(phid, W_activ, b_activ,
                                      out + (size_t)CM * 9);
}